// round 6
// baseline (speedup 1.0000x reference)
#include <cuda_runtime.h>
#include <math.h>

#define Bn 8
#define Nn 256
#define Dd 256
#define DHh 64
#define BND (Bn * Nn * DHh)      // 131072
#define BNr (Bn * Nn)            // 2048
#define PR 16                    // rows per block in prep kernels

// scratch: Qn,Kn,Vn,Q,K,V
__device__ float g_np[6 * BND];
// folded-weight per-row vectors
__device__ float g_u[BNr * Dd];    // Wk_n2e @ Qn_i
__device__ float g_v[BNr * Dd];    // Wq_e2n @ Kn_j
__device__ float g_c[BNr];         // bk_n2e . Qn_i
__device__ float g_d[BNr];         // bq_e2n . Kn_j
// transposed weights (h-major)
__device__ float g_Wkt[DHh * Dd];
__device__ float g_Wqt[DHh * Dd];
// K transposed per batch: [b][d][j]
__device__ float g_Kt[Bn * DHh * Nn];

// Reduce two values across the warp in 6 shuffles.
__device__ __forceinline__ void dual_warp_sum(float& a, float& b_, int lane) {
    float send = (lane & 16) ? a : b_;
    float recv = __shfl_xor_sync(0xffffffffu, send, 16);
    float v = (lane & 16) ? (b_ + recv) : (a + recv);
    #pragma unroll
    for (int o = 8; o; o >>= 1) v += __shfl_xor_sync(0xffffffffu, v, o);
    float other = __shfl_xor_sync(0xffffffffu, v, 16);
    a  = (lane & 16) ? other : v;
    b_ = (lane & 16) ? v : other;
}

// ------------------------------------------------------------------
// 6 projections of x, 16 rows per block (weight reuse in L1/L2)
// grid = 128, block = 256
// ------------------------------------------------------------------
__global__ void proj_x_kernel(
    const float* __restrict__ x, const float* __restrict__ mask,
    const float* __restrict__ W0, const float* __restrict__ b0,
    const float* __restrict__ W1, const float* __restrict__ b1,
    const float* __restrict__ W2, const float* __restrict__ b2,
    const float* __restrict__ W3, const float* __restrict__ b3,
    const float* __restrict__ W4, const float* __restrict__ b4,
    const float* __restrict__ W5, const float* __restrict__ b5)
{
    int r0 = blockIdx.x * PR;
    int t = threadIdx.x;
    __shared__ float xs[PR][Dd];
    __shared__ float msk[PR];

    #pragma unroll
    for (int i = 0; i < PR; ++i)
        xs[i][t] = x[(size_t)(r0 + i) * Dd + t];
    if (t < PR) msk[t] = mask[r0 + t];
    __syncthreads();

    int h = t & 63, g = t >> 6;       // group g handles rows 4g..4g+3
    int base = g * 4;

    const float* Ws[6] = {W0, W1, W2, W3, W4, W5};
    const float* bs[6] = {b0, b1, b2, b3, b4, b5};

    #pragma unroll
    for (int p = 0; p < 6; ++p) {
        const float* W = Ws[p];
        float bias = bs[p][h];
        float a0 = bias, a1 = bias, a2 = bias, a3 = bias;
        #pragma unroll 4
        for (int k = 0; k < Dd; ++k) {
            float w = W[k * DHh + h];
            a0 = fmaf(xs[base + 0][k], w, a0);
            a1 = fmaf(xs[base + 1][k], w, a1);
            a2 = fmaf(xs[base + 2][k], w, a2);
            a3 = fmaf(xs[base + 3][k], w, a3);
        }
        float* dst = g_np + (size_t)p * BND + (size_t)(r0 + base) * DHh + h;
        dst[0 * DHh] = a0 * msk[base + 0];
        dst[1 * DHh] = a1 * msk[base + 1];
        dst[2 * DHh] = a2 * msk[base + 2];
        dst[3 * DHh] = a3 * msk[base + 3];
    }
}

__global__ void transpose_w_kernel(const float* __restrict__ Wk,
                                   const float* __restrict__ Wq)
{
    int h = blockIdx.x;
    int d = threadIdx.x;
    g_Wkt[h * Dd + d] = Wk[d * DHh + h];
    g_Wqt[h * Dd + d] = Wq[d * DHh + h];
}

// Kt[b][d][j] = K[b*Nn+j][d]   (K = g_np slot 4)
__global__ void kt_kernel()
{
    int b = blockIdx.x >> 3;
    int dg = (blockIdx.x & 7) * 8;    // 8 d's per block
    int t = threadIdx.x;
    const float* K = g_np + 4 * (size_t)BND + (size_t)b * Nn * DHh;
    #pragma unroll
    for (int dd = 0; dd < 8; ++dd) {
        int d = dg + dd;
        g_Kt[((size_t)b * DHh + d) * Nn + t] = K[(size_t)t * DHh + d];
    }
}

// u/v for 16 rows per block; Wkt/Wqt streamed once per block
// grid = 128, block = 256 (thread owns d)
__global__ void make_uv_kernel(const float* __restrict__ bk,
                               const float* __restrict__ bq)
{
    int r0 = blockIdx.x * PR;
    int t = threadIdx.x;
    __shared__ float qn[PR][DHh];
    __shared__ float kn[PR][DHh];

    #pragma unroll
    for (int i = 0; i < 4; ++i) {
        int idx = t + i * 256;            // 0..1023
        int row = idx >> 6, h = idx & 63;
        qn[row][h] = g_np[(size_t)(r0 + row) * DHh + h];
        kn[row][h] = g_np[(size_t)BND + (size_t)(r0 + row) * DHh + h];
    }
    __syncthreads();

    // u pass
    {
        float au[PR];
        #pragma unroll
        for (int i = 0; i < PR; ++i) au[i] = 0.f;
        #pragma unroll 4
        for (int h = 0; h < DHh; ++h) {
            float w = g_Wkt[h * Dd + t];
            #pragma unroll
            for (int i = 0; i < PR; ++i) au[i] = fmaf(w, qn[i][h], au[i]);
        }
        #pragma unroll
        for (int i = 0; i < PR; ++i)
            g_u[(size_t)(r0 + i) * Dd + t] = au[i];
    }
    // v pass
    {
        float av[PR];
        #pragma unroll
        for (int i = 0; i < PR; ++i) av[i] = 0.f;
        #pragma unroll 4
        for (int h = 0; h < DHh; ++h) {
            float w = g_Wqt[h * Dd + t];
            #pragma unroll
            for (int i = 0; i < PR; ++i) av[i] = fmaf(w, kn[i][h], av[i]);
        }
        #pragma unroll
        for (int i = 0; i < PR; ++i)
            g_v[(size_t)(r0 + i) * Dd + t] = av[i];
    }
    // bias dots
    if (t < PR) {
        float sc = 0.f;
        #pragma unroll 8
        for (int h = 0; h < DHh; ++h) sc = fmaf(bk[h], qn[t][h], sc);
        g_c[r0 + t] = sc;
    } else if (t >= 32 && t < 32 + PR) {
        int row = t - 32;
        float sd2 = 0.f;
        #pragma unroll 8
        for (int h = 0; h < DHh; ++h) sd2 = fmaf(bq[h], kn[row][h], sd2);
        g_d[r0 + row] = sd2;
    }
}

// ------------------------------------------------------------------
// Fused mega-kernel: per (b,i) block
//   phase 1: stream e (2 j's per warp-iter) -> e_new + online softmax sums
//   phase 2: n2n self attention row (logits via g_Kt, no smem tile)
//   phase 3: x_cross & final mix
// ------------------------------------------------------------------
__global__ void __launch_bounds__(256, 3) fused_kernel(
    const float* __restrict__ e, const float* __restrict__ mask,
    const float* __restrict__ Wv, const float* __restrict__ bv,
    const float* __restrict__ Wmix, const float* __restrict__ bmix,
    float* __restrict__ out_e, float* __restrict__ out_x)
{
    int r = blockIdx.x;
    int b = r >> 8;
    int t = threadIdx.x;
    int wid = t >> 5, lane = t & 31;

    __shared__ float s_sm[8][Dd];     // 8KB
    __shared__ float maskb_s[Nn];
    __shared__ float djs_s[Nn];
    __shared__ float mw[8], lw[8], tw[8];
    __shared__ float gsrow[Dd];
    __shared__ float gt_s;
    __shared__ float Q_s[DHh];
    __shared__ float att[Nn];
    __shared__ float red[256];
    __shared__ float part[4][DHh];
    __shared__ float xsf_s[DHh], xc_s[DHh];

    const float* Vn = g_np + 2 * (size_t)BND;

    maskb_s[t] = mask[b * Nn + t];
    djs_s[t]   = g_d[b * Nn + t];
    __syncthreads();

    int d0 = 4 * lane;
    int d1 = 128 + 4 * lane;
    int bN = b * Nn;

    const float4 u0  = *reinterpret_cast<const float4*>(g_u + (size_t)r * Dd + d0);
    const float4 u1  = *reinterpret_cast<const float4*>(g_u + (size_t)r * Dd + d1);
    const float4 vi0 = *reinterpret_cast<const float4*>(g_v + (size_t)r * Dd + d0);
    const float4 vi1 = *reinterpret_cast<const float4*>(g_v + (size_t)r * Dd + d1);
    const float c_i  = g_c[r];
    const float di   = g_d[r];
    const float xm_i = mask[r];
    const float2 vni = *reinterpret_cast<const float2*>(Vn + (size_t)r * DHh + 2 * lane);

    float m = -INFINITY, l = 0.f, tacc = 0.f;
    float4 s0 = make_float4(0.f, 0.f, 0.f, 0.f);
    float4 s1 = make_float4(0.f, 0.f, 0.f, 0.f);

    const float* erow = e + (size_t)r * Nn * Dd;

    // ---- phase 1: edge streaming, 2 j's per warp-iteration ----
    for (int it = 0; it < 16; ++it) {
        int ja = 2 * wid + it * 16;
        int jb = ja + 1;

        float4 ea0 = __ldcs(reinterpret_cast<const float4*>(erow + (size_t)ja * Dd + d0));
        float4 ea1 = __ldcs(reinterpret_cast<const float4*>(erow + (size_t)ja * Dd + d1));
        float4 eb0 = __ldcs(reinterpret_cast<const float4*>(erow + (size_t)jb * Dd + d0));
        float4 eb1 = __ldcs(reinterpret_cast<const float4*>(erow + (size_t)jb * Dd + d1));
        float4 va0 = *reinterpret_cast<const float4*>(g_v + (size_t)(bN + ja) * Dd + d0);
        float4 va1 = *reinterpret_cast<const float4*>(g_v + (size_t)(bN + ja) * Dd + d1);
        float4 vb0 = *reinterpret_cast<const float4*>(g_v + (size_t)(bN + jb) * Dd + d0);
        float4 vb1 = *reinterpret_cast<const float4*>(g_v + (size_t)(bN + jb) * Dd + d1);
        float2 vna = *reinterpret_cast<const float2*>(Vn + (size_t)(bN + ja) * DHh + 2 * lane);
        float2 vnb = *reinterpret_cast<const float2*>(Vn + (size_t)(bN + jb) * DHh + 2 * lane);

        // vdiff in place
        va0.x -= vi0.x; va0.y -= vi0.y; va0.z -= vi0.z; va0.w -= vi0.w;
        va1.x -= vi1.x; va1.y -= vi1.y; va1.z -= vi1.z; va1.w -= vi1.w;
        vb0.x -= vi0.x; vb0.y -= vi0.y; vb0.z -= vi0.z; vb0.w -= vi0.w;
        vb1.x -= vi1.x; vb1.y -= vi1.y; vb1.z -= vi1.z; vb1.w -= vi1.w;

        float dot0a, dotda, dot0b, dotdb;
        dot0a = ea0.x * u0.x;             dot0a = fmaf(ea0.y, u0.y, dot0a);
        dot0a = fmaf(ea0.z, u0.z, dot0a); dot0a = fmaf(ea0.w, u0.w, dot0a);
        dot0a = fmaf(ea1.x, u1.x, dot0a); dot0a = fmaf(ea1.y, u1.y, dot0a);
        dot0a = fmaf(ea1.z, u1.z, dot0a); dot0a = fmaf(ea1.w, u1.w, dot0a);
        dotda = ea0.x * va0.x;             dotda = fmaf(ea0.y, va0.y, dotda);
        dotda = fmaf(ea0.z, va0.z, dotda); dotda = fmaf(ea0.w, va0.w, dotda);
        dotda = fmaf(ea1.x, va1.x, dotda); dotda = fmaf(ea1.y, va1.y, dotda);
        dotda = fmaf(ea1.z, va1.z, dotda); dotda = fmaf(ea1.w, va1.w, dotda);
        dot0b = eb0.x * u0.x;             dot0b = fmaf(eb0.y, u0.y, dot0b);
        dot0b = fmaf(eb0.z, u0.z, dot0b); dot0b = fmaf(eb0.w, u0.w, dot0b);
        dot0b = fmaf(eb1.x, u1.x, dot0b); dot0b = fmaf(eb1.y, u1.y, dot0b);
        dot0b = fmaf(eb1.z, u1.z, dot0b); dot0b = fmaf(eb1.w, u1.w, dot0b);
        dotdb = eb0.x * vb0.x;             dotdb = fmaf(eb0.y, vb0.y, dotdb);
        dotdb = fmaf(eb0.z, vb0.z, dotdb); dotdb = fmaf(eb0.w, vb0.w, dotdb);
        dotdb = fmaf(eb1.x, vb1.x, dotdb); dotdb = fmaf(eb1.y, vb1.y, dotdb);
        dotdb = fmaf(eb1.z, vb1.z, dotdb); dotdb = fmaf(eb1.w, vb1.w, dotdb);

        dual_warp_sum(dot0a, dotda, lane);
        dual_warp_sum(dot0b, dotdb, lane);

        // --- j = ja ---
        {
            float em = xm_i * maskb_s[ja];
            bool am = em > 0.f;
            float sc = am ? (dot0a + c_i) * em * 0.125f : -1e9f;
            float mn = fmaxf(m, sc);
            float alpha = __expf(m - mn);
            float pv = __expf(sc - mn);
            l = l * alpha + pv;
            float pve = pv * em;
            tacc = tacc * alpha + pve;
            s0.x = fmaf(s0.x, alpha, pve * ea0.x);
            s0.y = fmaf(s0.y, alpha, pve * ea0.y);
            s0.z = fmaf(s0.z, alpha, pve * ea0.z);
            s0.w = fmaf(s0.w, alpha, pve * ea0.w);
            s1.x = fmaf(s1.x, alpha, pve * ea1.x);
            s1.y = fmaf(s1.y, alpha, pve * ea1.y);
            s1.z = fmaf(s1.z, alpha, pve * ea1.z);
            s1.w = fmaf(s1.w, alpha, pve * ea1.w);
            m = mn;
            float o0 = 0.f, o1 = 0.f;
            if (am) {
                float arg = (dotda + djs_s[ja] - di) * em * 0.125f;
                float ai = 1.f / (1.f + __expf(-arg));
                float aj = 1.f - ai;
                o0 = (ai * vna.x + aj * vni.x) * em;
                o1 = (ai * vna.y + aj * vni.y) * em;
            }
            __stcg(reinterpret_cast<float2*>(out_e + ((size_t)r * Nn + ja) * DHh + 2 * lane),
                   make_float2(o0, o1));
        }
        // --- j = jb ---
        {
            float em = xm_i * maskb_s[jb];
            bool am = em > 0.f;
            float sc = am ? (dot0b + c_i) * em * 0.125f : -1e9f;
            float mn = fmaxf(m, sc);
            float alpha = __expf(m - mn);
            float pv = __expf(sc - mn);
            l = l * alpha + pv;
            float pve = pv * em;
            tacc = tacc * alpha + pve;
            s0.x = fmaf(s0.x, alpha, pve * eb0.x);
            s0.y = fmaf(s0.y, alpha, pve * eb0.y);
            s0.z = fmaf(s0.z, alpha, pve * eb0.z);
            s0.w = fmaf(s0.w, alpha, pve * eb0.w);
            s1.x = fmaf(s1.x, alpha, pve * eb1.x);
            s1.y = fmaf(s1.y, alpha, pve * eb1.y);
            s1.z = fmaf(s1.z, alpha, pve * eb1.z);
            s1.w = fmaf(s1.w, alpha, pve * eb1.w);
            m = mn;
            float o0 = 0.f, o1 = 0.f;
            if (am) {
                float arg = (dotdb + djs_s[jb] - di) * em * 0.125f;
                float ai = 1.f / (1.f + __expf(-arg));
                float aj = 1.f - ai;
                o0 = (ai * vnb.x + aj * vni.x) * em;
                o1 = (ai * vnb.y + aj * vni.y) * em;
            }
            __stcg(reinterpret_cast<float2*>(out_e + ((size_t)r * Nn + jb) * DHh + 2 * lane),
                   make_float2(o0, o1));
        }
    }

    // merge the 8 warps' online-softmax partials
    s_sm[wid][d0 + 0] = s0.x; s_sm[wid][d0 + 1] = s0.y;
    s_sm[wid][d0 + 2] = s0.z; s_sm[wid][d0 + 3] = s0.w;
    s_sm[wid][d1 + 0] = s1.x; s_sm[wid][d1 + 1] = s1.y;
    s_sm[wid][d1 + 2] = s1.z; s_sm[wid][d1 + 3] = s1.w;
    if (lane == 0) { mw[wid] = m; lw[wid] = l; tw[wid] = tacc; }
    __syncthreads();

    {
        float gm = mw[0];
        #pragma unroll
        for (int w = 1; w < 8; ++w) gm = fmaxf(gm, mw[w]);
        float gl = 0.f, gt = 0.f, gs = 0.f;
        #pragma unroll
        for (int w = 0; w < 8; ++w) {
            float sc2 = __expf(mw[w] - gm);
            gl = fmaf(lw[w], sc2, gl);
            gt = fmaf(tw[w], sc2, gt);
            gs = fmaf(s_sm[w][t], sc2, gs);
        }
        float invl = 1.f / gl;
        gsrow[t] = gs * invl;
        if (t == 0) gt_s = gt * invl;
    }

    // ---- phase 2: n2n self attention via g_Kt ----
    const float* Q = g_np + 3 * (size_t)BND;
    const float* V = g_np + 5 * (size_t)BND;

    if (t < DHh) Q_s[t] = Q[(size_t)r * DHh + t];
    __syncthreads();

    float lg;
    {
        const float* ktb = g_Kt + (size_t)b * DHh * Nn;
        float acc = 0.f;
        #pragma unroll 8
        for (int d = 0; d < DHh; ++d)
            acc = fmaf(Q_s[d], ktb[(size_t)d * Nn + t], acc);
        lg = acc;
    }

    // masked softmax over 256 logits (thread t owns j=t)
    {
        bool am = (xm_i * maskb_s[t]) > 0.f;
        lg = am ? lg * 0.125f : -1e9f;
        float wmax = lg;
        #pragma unroll
        for (int o = 16; o; o >>= 1)
            wmax = fmaxf(wmax, __shfl_xor_sync(0xffffffffu, wmax, o));
        if (lane == 0) red[wid] = wmax;
        __syncthreads();
        float gmax = red[0];
        #pragma unroll
        for (int w = 1; w < 8; ++w) gmax = fmaxf(gmax, red[w]);
        float ex = __expf(lg - gmax);
        float wsum = ex;
        #pragma unroll
        for (int o = 16; o; o >>= 1)
            wsum += __shfl_xor_sync(0xffffffffu, wsum, o);
        if (lane == 0) red[8 + wid] = wsum;
        __syncthreads();
        float gsum = 0.f;
        #pragma unroll
        for (int w = 0; w < 8; ++w) gsum += red[8 + w];
        att[t] = ex / gsum;
    }
    __syncthreads();

    // PV: quarter q handles j in [64q, 64q+64)
    {
        int q = t >> 6, h = t & 63;
        float acc = 0.f;
        const float* Vb = V + (size_t)(bN + q * 64) * DHh + h;
        #pragma unroll 8
        for (int jj = 0; jj < 64; ++jj)
            acc = fmaf(att[q * 64 + jj], Vb[(size_t)jj * DHh], acc);
        part[q][h] = acc;
    }
    __syncthreads();
    if (t < DHh)
        xsf_s[t] = (part[0][t] + part[1][t] + part[2][t] + part[3][t]) * xm_i;
    __syncthreads();

    // ---- phase 3: x_cross = gsrow@Wv + gt*bv ; out = [xc,xs]@Wmix + bmix ----
    {
        int q = t >> 6, h = t & 63;
        float acc = (q == 0) ? gt_s * bv[h] : 0.f;
        #pragma unroll 8
        for (int d = 0; d < 64; ++d)
            acc = fmaf(gsrow[q * 64 + d], Wv[(q * 64 + d) * DHh + h], acc);
        part[q][h] = acc;
    }
    __syncthreads();
    if (t < DHh) xc_s[t] = part[0][t] + part[1][t] + part[2][t] + part[3][t];
    __syncthreads();

    if (t < 128) {
        int half = t >> 6, hh = t & 63;
        float o = (half == 0) ? bmix[hh] : 0.f;
        #pragma unroll 8
        for (int k = 0; k < 64; ++k) {
            float src = (half == 0) ? xc_s[k] : xsf_s[k];
            o = fmaf(src, Wmix[(half * 64 + k) * DHh + hh], o);
        }
        part[half][hh] = o;
    }
    __syncthreads();
    if (t < DHh) out_x[(size_t)r * DHh + t] = part[0][t] + part[1][t];
}

extern "C" void kernel_launch(void* const* d_in, const int* in_sizes, int n_in,
                              void* d_out, int out_size)
{
    const float* x       = (const float*)d_in[0];
    const float* e       = (const float*)d_in[1];
    const float* mask    = (const float*)d_in[2];
    const float* W_n2e_q = (const float*)d_in[3];  const float* b_n2e_q = (const float*)d_in[4];
    const float* W_n2e_k = (const float*)d_in[5];  const float* b_n2e_k = (const float*)d_in[6];
    const float* W_n2e_v = (const float*)d_in[7];  const float* b_n2e_v = (const float*)d_in[8];
    const float* W_e2n_q = (const float*)d_in[9];  const float* b_e2n_q = (const float*)d_in[10];
    const float* W_e2n_k = (const float*)d_in[11]; const float* b_e2n_k = (const float*)d_in[12];
    const float* W_e2n_v = (const float*)d_in[13]; const float* b_e2n_v = (const float*)d_in[14];
    const float* W_n2n_q = (const float*)d_in[15]; const float* b_n2n_q = (const float*)d_in[16];
    const float* W_n2n_k = (const float*)d_in[17]; const float* b_n2n_k = (const float*)d_in[18];
    const float* W_n2n_v = (const float*)d_in[19]; const float* b_n2n_v = (const float*)d_in[20];
    const float* W_mix   = (const float*)d_in[21]; const float* b_mix   = (const float*)d_in[22];

    float* out   = (float*)d_out;
    float* out_x = out;
    float* out_e = out + (size_t)Bn * Nn * DHh;

    proj_x_kernel<<<BNr / PR, 256>>>(x, mask,
        W_n2e_q, b_n2e_q,
        W_e2n_k, b_e2n_k,
        W_e2n_v, b_e2n_v,
        W_n2n_q, b_n2n_q,
        W_n2n_k, b_n2n_k,
        W_n2n_v, b_n2n_v);

    transpose_w_kernel<<<DHh, Dd>>>(W_n2e_k, W_e2n_q);
    kt_kernel<<<64, 256>>>();
    make_uv_kernel<<<BNr / PR, 256>>>(b_n2e_k, b_e2n_q);

    fused_kernel<<<BNr, 256>>>(e, mask,
        W_n2e_v, b_n2e_v, W_mix, b_mix, out_e, out_x);
}

// round 7
// speedup vs baseline: 1.0240x; 1.0240x over previous
#include <cuda_runtime.h>
#include <math.h>

#define Bn 8
#define Nn 256
#define Dd 256
#define DHh 64
#define BND (Bn * Nn * DHh)      // 131072
#define BNr (Bn * Nn)            // 2048
#define PR 16                    // rows per block in proj kernel
#define PRUV 4                   // rows per block in make_uv

// scratch: Qn,Kn,Vn,Q,K,V
__device__ float g_np[6 * BND];
// folded-weight per-row vectors
__device__ float g_u[BNr * Dd];    // Wk_n2e @ Qn_i
__device__ float g_v[BNr * Dd];    // Wq_e2n @ Kn_j
__device__ float g_c[BNr];         // bk_n2e . Qn_i
__device__ float g_d[BNr];         // bq_e2n . Kn_j
// transposed weights (h-major)
__device__ float g_Wkt[DHh * Dd];
__device__ float g_Wqt[DHh * Dd];
// K transposed per batch: [b][d][j]
__device__ float g_Kt[Bn * DHh * Nn];

// Reduce two values across the warp in 6 shuffles.
__device__ __forceinline__ void dual_warp_sum(float& a, float& b_, int lane) {
    float send = (lane & 16) ? a : b_;
    float recv = __shfl_xor_sync(0xffffffffu, send, 16);
    float v = (lane & 16) ? (b_ + recv) : (a + recv);
    #pragma unroll
    for (int o = 8; o; o >>= 1) v += __shfl_xor_sync(0xffffffffu, v, o);
    float other = __shfl_xor_sync(0xffffffffu, v, 16);
    a  = (lane & 16) ? other : v;
    b_ = (lane & 16) ? v : other;
}

// ------------------------------------------------------------------
// 6 projections of x, 16 rows per block
// ------------------------------------------------------------------
__global__ void proj_x_kernel(
    const float* __restrict__ x, const float* __restrict__ mask,
    const float* __restrict__ W0, const float* __restrict__ b0,
    const float* __restrict__ W1, const float* __restrict__ b1,
    const float* __restrict__ W2, const float* __restrict__ b2,
    const float* __restrict__ W3, const float* __restrict__ b3,
    const float* __restrict__ W4, const float* __restrict__ b4,
    const float* __restrict__ W5, const float* __restrict__ b5)
{
    int r0 = blockIdx.x * PR;
    int t = threadIdx.x;
    __shared__ float xs[PR][Dd];
    __shared__ float msk[PR];

    #pragma unroll
    for (int i = 0; i < PR; ++i)
        xs[i][t] = x[(size_t)(r0 + i) * Dd + t];
    if (t < PR) msk[t] = mask[r0 + t];
    __syncthreads();

    int h = t & 63, g = t >> 6;       // group g handles rows 4g..4g+3
    int base = g * 4;

    const float* Ws[6] = {W0, W1, W2, W3, W4, W5};
    const float* bs[6] = {b0, b1, b2, b3, b4, b5};

    #pragma unroll
    for (int p = 0; p < 6; ++p) {
        const float* W = Ws[p];
        float bias = bs[p][h];
        float a0 = bias, a1 = bias, a2 = bias, a3 = bias;
        #pragma unroll 4
        for (int k = 0; k < Dd; ++k) {
            float w = W[k * DHh + h];
            a0 = fmaf(xs[base + 0][k], w, a0);
            a1 = fmaf(xs[base + 1][k], w, a1);
            a2 = fmaf(xs[base + 2][k], w, a2);
            a3 = fmaf(xs[base + 3][k], w, a3);
        }
        float* dst = g_np + (size_t)p * BND + (size_t)(r0 + base) * DHh + h;
        dst[0 * DHh] = a0 * msk[base + 0];
        dst[1 * DHh] = a1 * msk[base + 1];
        dst[2 * DHh] = a2 * msk[base + 2];
        dst[3 * DHh] = a3 * msk[base + 3];
    }
}

__global__ void transpose_w_kernel(const float* __restrict__ Wk,
                                   const float* __restrict__ Wq)
{
    int h = blockIdx.x;
    int d = threadIdx.x;
    g_Wkt[h * Dd + d] = Wk[d * DHh + h];
    g_Wqt[h * Dd + d] = Wq[d * DHh + h];
}

// Kt[b][d][j] = K[b*Nn+j][d]   (K = g_np slot 4)
__global__ void kt_kernel()
{
    int b = blockIdx.x >> 3;
    int dg = (blockIdx.x & 7) * 8;    // 8 d's per block
    int t = threadIdx.x;
    const float* K = g_np + 4 * (size_t)BND + (size_t)b * Nn * DHh;
    #pragma unroll
    for (int dd = 0; dd < 8; ++dd) {
        int d = dg + dd;
        g_Kt[((size_t)b * DHh + d) * Nn + t] = K[(size_t)t * DHh + d];
    }
}

// u/v for 4 rows per block (512 blocks for occupancy)
__global__ void make_uv_kernel(const float* __restrict__ bk,
                               const float* __restrict__ bq)
{
    int r0 = blockIdx.x * PRUV;
    int t = threadIdx.x;
    __shared__ float qn[PRUV][DHh];
    __shared__ float kn[PRUV][DHh];

    if (t < PRUV * DHh) {
        int row = t >> 6, h = t & 63;
        qn[row][h] = g_np[(size_t)(r0 + row) * DHh + h];
        kn[row][h] = g_np[(size_t)BND + (size_t)(r0 + row) * DHh + h];
    }
    __syncthreads();

    float au[PRUV], av[PRUV];
    #pragma unroll
    for (int i = 0; i < PRUV; ++i) { au[i] = 0.f; av[i] = 0.f; }
    #pragma unroll 4
    for (int h = 0; h < DHh; ++h) {
        float wu = g_Wkt[h * Dd + t];
        float wv = g_Wqt[h * Dd + t];
        #pragma unroll
        for (int i = 0; i < PRUV; ++i) {
            au[i] = fmaf(wu, qn[i][h], au[i]);
            av[i] = fmaf(wv, kn[i][h], av[i]);
        }
    }
    #pragma unroll
    for (int i = 0; i < PRUV; ++i) {
        g_u[(size_t)(r0 + i) * Dd + t] = au[i];
        g_v[(size_t)(r0 + i) * Dd + t] = av[i];
    }

    if (t < PRUV) {
        float sc = 0.f;
        #pragma unroll 8
        for (int h = 0; h < DHh; ++h) sc = fmaf(bk[h], qn[t][h], sc);
        g_c[r0 + t] = sc;
    } else if (t >= 32 && t < 32 + PRUV) {
        int row = t - 32;
        float sd2 = 0.f;
        #pragma unroll 8
        for (int h = 0; h < DHh; ++h) sd2 = fmaf(bq[h], kn[row][h], sd2);
        g_d[r0 + row] = sd2;
    }
}

// ------------------------------------------------------------------
// Fused mega-kernel: per (b,i) block
//   phase 1: R4-style pipelined edge stream (1 j/warp-iter, prefetch)
//   phase 2: n2n self attention row (logits via g_Kt)
//   phase 3: x_cross & final mix
// ------------------------------------------------------------------
__global__ void __launch_bounds__(256, 3) fused_kernel(
    const float* __restrict__ e, const float* __restrict__ mask,
    const float* __restrict__ Wv, const float* __restrict__ bv,
    const float* __restrict__ Wmix, const float* __restrict__ bmix,
    float* __restrict__ out_e, float* __restrict__ out_x)
{
    int r = blockIdx.x;
    int b = r >> 8;
    int t = threadIdx.x;
    int wid = t >> 5, lane = t & 31;

    __shared__ float s_sm[8][Dd];
    __shared__ float maskb_s[Nn];
    __shared__ float djs_s[Nn];
    __shared__ float mw[8], lw[8], tw[8];
    __shared__ float gsrow[Dd];
    __shared__ float gt_s;
    __shared__ float Q_s[DHh];
    __shared__ float att[Nn];
    __shared__ float red[256];
    __shared__ float part[4][DHh];
    __shared__ float xsf_s[DHh], xc_s[DHh];

    const float* Vn = g_np + 2 * (size_t)BND;

    maskb_s[t] = mask[b * Nn + t];
    djs_s[t]   = g_d[b * Nn + t];
    __syncthreads();

    int d0 = 4 * lane;
    int d1 = 128 + 4 * lane;
    int bN = b * Nn;

    const float4 u0  = *reinterpret_cast<const float4*>(g_u + (size_t)r * Dd + d0);
    const float4 u1  = *reinterpret_cast<const float4*>(g_u + (size_t)r * Dd + d1);
    const float4 vi0 = *reinterpret_cast<const float4*>(g_v + (size_t)r * Dd + d0);
    const float4 vi1 = *reinterpret_cast<const float4*>(g_v + (size_t)r * Dd + d1);
    const float c_i  = g_c[r];
    const float di   = g_d[r];
    const float xm_i = mask[r];
    const float2 vni = *reinterpret_cast<const float2*>(Vn + (size_t)r * DHh + 2 * lane);

    float m = -INFINITY, l = 0.f, tacc = 0.f;
    float4 s0 = make_float4(0.f, 0.f, 0.f, 0.f);
    float4 s1 = make_float4(0.f, 0.f, 0.f, 0.f);

    const float* erow = e + (size_t)r * Nn * Dd;

    // ---- phase 1: edge streaming, prefetch pipeline (R4 style) ----
    int j = wid;
    float4 e0 = __ldcs(reinterpret_cast<const float4*>(erow + (size_t)j * Dd + d0));
    float4 e1 = __ldcs(reinterpret_cast<const float4*>(erow + (size_t)j * Dd + d1));
    float4 vj0 = *reinterpret_cast<const float4*>(g_v + (size_t)(bN + j) * Dd + d0);
    float4 vj1 = *reinterpret_cast<const float4*>(g_v + (size_t)(bN + j) * Dd + d1);
    float2 vnj = *reinterpret_cast<const float2*>(Vn + (size_t)(bN + j) * DHh + 2 * lane);

    for (; j < Nn; ) {
        int jn = j + 8;
        float4 ne0, ne1, nvj0, nvj1; float2 nvnj;
        if (jn < Nn) {
            ne0 = __ldcs(reinterpret_cast<const float4*>(erow + (size_t)jn * Dd + d0));
            ne1 = __ldcs(reinterpret_cast<const float4*>(erow + (size_t)jn * Dd + d1));
            nvj0 = *reinterpret_cast<const float4*>(g_v + (size_t)(bN + jn) * Dd + d0);
            nvj1 = *reinterpret_cast<const float4*>(g_v + (size_t)(bN + jn) * Dd + d1);
            nvnj = *reinterpret_cast<const float2*>(Vn + (size_t)(bN + jn) * DHh + 2 * lane);
        }
        float xm_j = maskb_s[j];
        float dj   = djs_s[j];

        // vdiff = v_j - v_i
        float4 w0, w1;
        w0.x = vj0.x - vi0.x; w0.y = vj0.y - vi0.y;
        w0.z = vj0.z - vi0.z; w0.w = vj0.w - vi0.w;
        w1.x = vj1.x - vi1.x; w1.y = vj1.y - vi1.y;
        w1.z = vj1.z - vi1.z; w1.w = vj1.w - vi1.w;

        float dot0, dotd;
        dot0 = e0.x * u0.x;              dot0 = fmaf(e0.y, u0.y, dot0);
        dot0 = fmaf(e0.z, u0.z, dot0);   dot0 = fmaf(e0.w, u0.w, dot0);
        dot0 = fmaf(e1.x, u1.x, dot0);   dot0 = fmaf(e1.y, u1.y, dot0);
        dot0 = fmaf(e1.z, u1.z, dot0);   dot0 = fmaf(e1.w, u1.w, dot0);
        dotd = e0.x * w0.x;              dotd = fmaf(e0.y, w0.y, dotd);
        dotd = fmaf(e0.z, w0.z, dotd);   dotd = fmaf(e0.w, w0.w, dotd);
        dotd = fmaf(e1.x, w1.x, dotd);   dotd = fmaf(e1.y, w1.y, dotd);
        dotd = fmaf(e1.z, w1.z, dotd);   dotd = fmaf(e1.w, w1.w, dotd);

        dual_warp_sum(dot0, dotd, lane);

        float em = xm_i * xm_j;
        bool am = em > 0.f;

        // n2e online softmax + weighted-e accumulation
        float sc = am ? (dot0 + c_i) * em * 0.125f : -1e9f;
        float mn = fmaxf(m, sc);
        float alpha = __expf(m - mn);
        float pv = __expf(sc - mn);
        l = l * alpha + pv;
        float pve = pv * em;
        tacc = tacc * alpha + pve;
        s0.x = fmaf(s0.x, alpha, pve * e0.x);
        s0.y = fmaf(s0.y, alpha, pve * e0.y);
        s0.z = fmaf(s0.z, alpha, pve * e0.z);
        s0.w = fmaf(s0.w, alpha, pve * e0.w);
        s1.x = fmaf(s1.x, alpha, pve * e1.x);
        s1.y = fmaf(s1.y, alpha, pve * e1.y);
        s1.z = fmaf(s1.z, alpha, pve * e1.z);
        s1.w = fmaf(s1.w, alpha, pve * e1.w);
        m = mn;

        // e2n gating -> e_new: ai = sigmoid((dotd + dj - di)*em/8)
        float o0 = 0.f, o1 = 0.f;
        if (am) {
            float arg = (dotd + dj - di) * em * 0.125f;
            float ai = 1.f / (1.f + __expf(-arg));
            float aj = 1.f - ai;
            o0 = (ai * vnj.x + aj * vni.x) * em;
            o1 = (ai * vnj.y + aj * vni.y) * em;
        }
        __stcg(reinterpret_cast<float2*>(out_e + ((size_t)r * Nn + j) * DHh + 2 * lane),
               make_float2(o0, o1));

        j = jn;
        e0 = ne0; e1 = ne1; vj0 = nvj0; vj1 = nvj1; vnj = nvnj;
    }

    // merge the 8 warps' online-softmax partials
    s_sm[wid][d0 + 0] = s0.x; s_sm[wid][d0 + 1] = s0.y;
    s_sm[wid][d0 + 2] = s0.z; s_sm[wid][d0 + 3] = s0.w;
    s_sm[wid][d1 + 0] = s1.x; s_sm[wid][d1 + 1] = s1.y;
    s_sm[wid][d1 + 2] = s1.z; s_sm[wid][d1 + 3] = s1.w;
    if (lane == 0) { mw[wid] = m; lw[wid] = l; tw[wid] = tacc; }
    __syncthreads();

    {
        float gm = mw[0];
        #pragma unroll
        for (int w = 1; w < 8; ++w) gm = fmaxf(gm, mw[w]);
        float gl = 0.f, gt = 0.f, gs = 0.f;
        #pragma unroll
        for (int w = 0; w < 8; ++w) {
            float sc2 = __expf(mw[w] - gm);
            gl = fmaf(lw[w], sc2, gl);
            gt = fmaf(tw[w], sc2, gt);
            gs = fmaf(s_sm[w][t], sc2, gs);
        }
        float invl = 1.f / gl;
        gsrow[t] = gs * invl;
        if (t == 0) gt_s = gt * invl;
    }

    // ---- phase 2: n2n self attention via g_Kt ----
    const float* Q = g_np + 3 * (size_t)BND;
    const float* V = g_np + 5 * (size_t)BND;

    if (t < DHh) Q_s[t] = Q[(size_t)r * DHh + t];
    __syncthreads();

    float lg;
    {
        const float* ktb = g_Kt + (size_t)b * DHh * Nn;
        float acc = 0.f;
        #pragma unroll 8
        for (int d = 0; d < DHh; ++d)
            acc = fmaf(Q_s[d], ktb[(size_t)d * Nn + t], acc);
        lg = acc;
    }

    // masked softmax over 256 logits (thread t owns j=t)
    {
        bool am = (xm_i * maskb_s[t]) > 0.f;
        lg = am ? lg * 0.125f : -1e9f;
        float wmax = lg;
        #pragma unroll
        for (int o = 16; o; o >>= 1)
            wmax = fmaxf(wmax, __shfl_xor_sync(0xffffffffu, wmax, o));
        if (lane == 0) red[wid] = wmax;
        __syncthreads();
        float gmax = red[0];
        #pragma unroll
        for (int w = 1; w < 8; ++w) gmax = fmaxf(gmax, red[w]);
        float ex = __expf(lg - gmax);
        float wsum = ex;
        #pragma unroll
        for (int o = 16; o; o >>= 1)
            wsum += __shfl_xor_sync(0xffffffffu, wsum, o);
        if (lane == 0) red[8 + wid] = wsum;
        __syncthreads();
        float gsum = 0.f;
        #pragma unroll
        for (int w = 0; w < 8; ++w) gsum += red[8 + w];
        att[t] = ex / gsum;
    }
    __syncthreads();

    // PV: quarter q handles j in [64q, 64q+64)
    {
        int q = t >> 6, h = t & 63;
        float acc = 0.f;
        const float* Vb = V + (size_t)(bN + q * 64) * DHh + h;
        #pragma unroll 8
        for (int jj = 0; jj < 64; ++jj)
            acc = fmaf(att[q * 64 + jj], Vb[(size_t)jj * DHh], acc);
        part[q][h] = acc;
    }
    __syncthreads();
    if (t < DHh)
        xsf_s[t] = (part[0][t] + part[1][t] + part[2][t] + part[3][t]) * xm_i;
    __syncthreads();

    // ---- phase 3: x_cross = gsrow@Wv + gt*bv ; out = [xc,xs]@Wmix + bmix ----
    {
        int q = t >> 6, h = t & 63;
        float acc = (q == 0) ? gt_s * bv[h] : 0.f;
        #pragma unroll 8
        for (int d = 0; d < 64; ++d)
            acc = fmaf(gsrow[q * 64 + d], Wv[(q * 64 + d) * DHh + h], acc);
        part[q][h] = acc;
    }
    __syncthreads();
    if (t < DHh) xc_s[t] = part[0][t] + part[1][t] + part[2][t] + part[3][t];
    __syncthreads();

    if (t < 128) {
        int half = t >> 6, hh = t & 63;
        float o = (half == 0) ? bmix[hh] : 0.f;
        #pragma unroll 8
        for (int k = 0; k < 64; ++k) {
            float src = (half == 0) ? xc_s[k] : xsf_s[k];
            o = fmaf(src, Wmix[(half * 64 + k) * DHh + hh], o);
        }
        part[half][hh] = o;
    }
    __syncthreads();
    if (t < DHh) out_x[(size_t)r * DHh + t] = part[0][t] + part[1][t];
}

extern "C" void kernel_launch(void* const* d_in, const int* in_sizes, int n_in,
                              void* d_out, int out_size)
{
    const float* x       = (const float*)d_in[0];
    const float* e       = (const float*)d_in[1];
    const float* mask    = (const float*)d_in[2];
    const float* W_n2e_q = (const float*)d_in[3];  const float* b_n2e_q = (const float*)d_in[4];
    const float* W_n2e_k = (const float*)d_in[5];  const float* b_n2e_k = (const float*)d_in[6];
    const float* W_n2e_v = (const float*)d_in[7];  const float* b_n2e_v = (const float*)d_in[8];
    const float* W_e2n_q = (const float*)d_in[9];  const float* b_e2n_q = (const float*)d_in[10];
    const float* W_e2n_k = (const float*)d_in[11]; const float* b_e2n_k = (const float*)d_in[12];
    const float* W_e2n_v = (const float*)d_in[13]; const float* b_e2n_v = (const float*)d_in[14];
    const float* W_n2n_q = (const float*)d_in[15]; const float* b_n2n_q = (const float*)d_in[16];
    const float* W_n2n_k = (const float*)d_in[17]; const float* b_n2n_k = (const float*)d_in[18];
    const float* W_n2n_v = (const float*)d_in[19]; const float* b_n2n_v = (const float*)d_in[20];
    const float* W_mix   = (const float*)d_in[21]; const float* b_mix   = (const float*)d_in[22];

    float* out   = (float*)d_out;
    float* out_x = out;
    float* out_e = out + (size_t)Bn * Nn * DHh;

    proj_x_kernel<<<BNr / PR, 256>>>(x, mask,
        W_n2e_q, b_n2e_q,
        W_e2n_k, b_e2n_k,
        W_e2n_v, b_e2n_v,
        W_n2n_q, b_n2n_q,
        W_n2n_k, b_n2n_k,
        W_n2n_v, b_n2n_v);

    transpose_w_kernel<<<DHh, Dd>>>(W_n2e_k, W_e2n_q);
    kt_kernel<<<64, 256>>>();
    make_uv_kernel<<<BNr / PRUV, 256>>>(b_n2e_k, b_e2n_q);

    fused_kernel<<<BNr, 256>>>(e, mask,
        W_n2e_v, b_n2e_v, W_mix, b_mix, out_e, out_x);
}